// round 1
// baseline (speedup 1.0000x reference)
#include <cuda_runtime.h>
#include <cuda_bf16.h>

// Piecewise-linear LUT (sigmoid table, 65 knots on uniform grid [-8,8], h=0.25).
// Replicates jnp.searchsorted(side='right')-1 semantics exactly via analytic
// index + one-step fixup against the actual table values.
//
// Streaming, HBM-bound: float4 loads/stores, table + slopes staged in shared.

#define NPTS 65
#define NSEG 64

__device__ __forceinline__ float eval_pwl(float xv,
                                          const float* __restrict__ s_xs,
                                          const float* __restrict__ s_ys,
                                          const float* __restrict__ s_a,
                                          float x_last_seg)
{
    // Analytic segment index on the uniform grid; clamp to sentinel range.
    int idx = (int)floorf((xv + 8.0f) * 4.0f);
    idx = min(max(idx, -1), NSEG);   // idx in [-1, 64]

    // One-step fixup for float rounding at knots (grid values are fp32-exact,
    // but (x+8) rounds; one correction step suffices).
    if (idx >= 0 && xv < s_xs[idx]) {
        idx -= 1;
    } else if (idx < NSEG && xv >= s_xs[idx + 1]) {
        idx += 1;
    }

    bool in_range = (idx >= 0) && (idx <= NSEG - 1);
    int s = min(max(idx, 0), NSEG - 1);

    // a*x + b with b = y0 - a*x0  ->  fma(a, x - x0, y0)
    float f = in_range ? fmaf(s_a[s], xv - s_xs[s], s_ys[s]) : 0.0f;

    // Reference quirk: add 1 whenever x >= xs[n-2] (even inside last segment).
    f += (xv >= x_last_seg) ? 1.0f : 0.0f;
    return f;
}

__global__ void __launch_bounds__(256)
cSigmoid_pwl_kernel(const float4* __restrict__ x4,
                    const float*  __restrict__ table,  // [65][2] = (xs, ys)
                    float4* __restrict__ out4,
                    int n4)
{
    __shared__ float s_xs[NPTS];
    __shared__ float s_ys[NPTS];
    __shared__ float s_a[NSEG];

    int t = threadIdx.x;
    if (t < NPTS) {
        s_xs[t] = table[2 * t + 0];
        s_ys[t] = table[2 * t + 1];
    }
    __syncthreads();
    if (t < NSEG) {
        s_a[t] = (s_ys[t + 1] - s_ys[t]) / (s_xs[t + 1] - s_xs[t]);
    }
    __syncthreads();

    float x_last_seg = s_xs[NPTS - 2];

    int i = blockIdx.x * blockDim.x + t;
    if (i >= n4) return;

    float4 v = x4[i];
    float4 r;
    r.x = eval_pwl(v.x, s_xs, s_ys, s_a, x_last_seg);
    r.y = eval_pwl(v.y, s_xs, s_ys, s_a, x_last_seg);
    r.z = eval_pwl(v.z, s_xs, s_ys, s_a, x_last_seg);
    r.w = eval_pwl(v.w, s_xs, s_ys, s_a, x_last_seg);
    out4[i] = r;
}

// Scalar tail kernel (n not divisible by 4). For this problem n = 8*4096*2048
// is divisible by 4, but keep it correct in general.
__global__ void cSigmoid_pwl_tail_kernel(const float* __restrict__ x,
                                         const float* __restrict__ table,
                                         float* __restrict__ out,
                                         int start, int n)
{
    __shared__ float s_xs[NPTS];
    __shared__ float s_ys[NPTS];
    __shared__ float s_a[NSEG];

    int t = threadIdx.x;
    if (t < NPTS) {
        s_xs[t] = table[2 * t + 0];
        s_ys[t] = table[2 * t + 1];
    }
    __syncthreads();
    if (t < NSEG) {
        s_a[t] = (s_ys[t + 1] - s_ys[t]) / (s_xs[t + 1] - s_xs[t]);
    }
    __syncthreads();

    float x_last_seg = s_xs[NPTS - 2];

    int i = start + blockIdx.x * blockDim.x + t;
    if (i < n) {
        out[i] = eval_pwl(x[i], s_xs, s_ys, s_a, x_last_seg);
    }
}

extern "C" void kernel_launch(void* const* d_in, const int* in_sizes, int n_in,
                              void* d_out, int out_size)
{
    const float* x     = (const float*)d_in[0];
    const float* table = (const float*)d_in[1];
    float* out         = (float*)d_out;

    int n  = in_sizes[0];
    int n4 = n / 4;

    if (n4 > 0) {
        int threads = 256;
        int blocks  = (n4 + threads - 1) / threads;
        cSigmoid_pwl_kernel<<<blocks, threads>>>(
            (const float4*)x, table, (float4*)out, n4);
    }

    int tail = n - n4 * 4;
    if (tail > 0) {
        cSigmoid_pwl_tail_kernel<<<1, 256>>>(x, table, out, n4 * 4, n);
    }
}